// round 4
// baseline (speedup 1.0000x reference)
#include <cuda_runtime.h>
#include <cuda_bf16.h>
#include <cstdint>

#define NE 8
#define DM 1024
#define DF 4096
#define NT 8192  // B*S

// CTA tile
#define TM 128
#define TN 256
#define TK 32

// SMEM layout (bytes)
#define SM_ROWTOK 0          // 128 ints
#define SM_BIAS   512        // 256 floats
#define SM_STAGE  2048
#define OFF_AH    0
#define OFF_AL    8192
#define OFF_BH    16384
#define OFF_BL    32768
#define STAGE_BYTES 49152
#define NSTAGE 4
#define SMEM_TOTAL (SM_STAGE + NSTAGE * STAGE_BYTES)   // 198656

// ---------------- static scratch ----------------
__device__ int g_cnt[NE];
__device__ int g_bucket[NE][NT];
__device__ __align__(256) __nv_bfloat16 g_xhi[(size_t)NT * DM];
__device__ __align__(256) __nv_bfloat16 g_xlo[(size_t)NT * DM];
__device__ __align__(256) __nv_bfloat16 g_hhi[(size_t)NT * DF];
__device__ __align__(256) __nv_bfloat16 g_hlo[(size_t)NT * DF];
__device__ __align__(256) __nv_bfloat16 g_w1hi[(size_t)NE * DF * DM];  // [e][n][k]
__device__ __align__(256) __nv_bfloat16 g_w1lo[(size_t)NE * DF * DM];
__device__ __align__(256) __nv_bfloat16 g_w2hi[(size_t)NE * DM * DF];  // [e][n][k]
__device__ __align__(256) __nv_bfloat16 g_w2lo[(size_t)NE * DM * DF];

// ---------------- PTX helpers ----------------
__device__ __forceinline__ uint32_t smem_u32(const void* p) {
    uint32_t a;
    asm("{ .reg .u64 t; cvta.to.shared.u64 t, %1; cvt.u32.u64 %0, t; }" : "=r"(a) : "l"(p));
    return a;
}
__device__ __forceinline__ void cp16(uint32_t dst, const void* src) {
    asm volatile("cp.async.cg.shared.global [%0], [%1], 16;" :: "r"(dst), "l"(src));
}
__device__ __forceinline__ void cp_commit() { asm volatile("cp.async.commit_group;" ::: "memory"); }
template <int N>
__device__ __forceinline__ void cp_wait() { asm volatile("cp.async.wait_group %0;" :: "n"(N) : "memory"); }

#define LDSM4(r0, r1, r2, r3, addr) \
    asm volatile("ldmatrix.sync.aligned.m8n8.x4.shared.b16 {%0,%1,%2,%3}, [%4];" \
                 : "=r"(r0), "=r"(r1), "=r"(r2), "=r"(r3) : "r"(addr))

#define MMA16816(d, a, b) \
    asm volatile("mma.sync.aligned.m16n8k16.row.col.f32.bf16.bf16.f32 " \
                 "{%0,%1,%2,%3},{%4,%5,%6,%7},{%8,%9},{%0,%1,%2,%3};" \
                 : "+f"((d)[0]), "+f"((d)[1]), "+f"((d)[2]), "+f"((d)[3]) \
                 : "r"((a)[0]), "r"((a)[1]), "r"((a)[2]), "r"((a)[3]), \
                   "r"((b)[0]), "r"((b)[1]))

// ---------------- routing ----------------
__global__ void zero_cnt_kernel() {
    if (threadIdx.x < NE) g_cnt[threadIdx.x] = 0;
}

__global__ void gate_route_kernel(const float* __restrict__ x,
                                  const float* __restrict__ gw,
                                  const float* __restrict__ gb) {
    int gtid = blockIdx.x * blockDim.x + threadIdx.x;
    int tok = gtid >> 5;
    int lane = gtid & 31;
    if (tok >= NT) return;
    const float* xr = x + (size_t)tok * DM;
    float acc[NE];
#pragma unroll
    for (int e = 0; e < NE; e++) acc[e] = 0.f;
    for (int d = lane; d < DM; d += 32) {
        float xv = xr[d];
        const float4* g4 = reinterpret_cast<const float4*>(gw + (size_t)d * NE);
        float4 a = g4[0], b = g4[1];
        acc[0] += xv * a.x; acc[1] += xv * a.y; acc[2] += xv * a.z; acc[3] += xv * a.w;
        acc[4] += xv * b.x; acc[5] += xv * b.y; acc[6] += xv * b.z; acc[7] += xv * b.w;
    }
#pragma unroll
    for (int e = 0; e < NE; e++) {
#pragma unroll
        for (int off = 16; off > 0; off >>= 1)
            acc[e] += __shfl_down_sync(0xffffffffu, acc[e], off);
    }
    if (lane == 0) {
        int best = 0;
        float bv = acc[0] + gb[0];
#pragma unroll
        for (int e = 1; e < NE; e++) {
            float v = acc[e] + gb[e];
            if (v > bv) { bv = v; best = e; }
        }
        int pos = atomicAdd(&g_cnt[best], 1);
        g_bucket[best][pos] = tok;
    }
}

// ---------------- fp32 -> (hi,lo) bf16 splits ----------------
__global__ void xsplit_kernel(const float* __restrict__ x,
                              __nv_bfloat16* __restrict__ hi,
                              __nv_bfloat16* __restrict__ lo, int n2) {
    for (int i = blockIdx.x * blockDim.x + threadIdx.x; i < n2; i += gridDim.x * blockDim.x) {
        float2 v = reinterpret_cast<const float2*>(x)[i];
        __nv_bfloat16 h0 = __float2bfloat16(v.x);
        __nv_bfloat16 h1 = __float2bfloat16(v.y);
        __nv_bfloat162 hv; hv.x = h0; hv.y = h1;
        reinterpret_cast<__nv_bfloat162*>(hi)[i] = hv;
        __nv_bfloat162 lv;
        lv.x = __float2bfloat16(v.x - __bfloat162float(h0));
        lv.y = __float2bfloat16(v.y - __bfloat162float(h1));
        reinterpret_cast<__nv_bfloat162*>(lo)[i] = lv;
    }
}

// W [e][K][N] fp32 -> Whi/Wlo [e][N][K] bf16 (tiled transpose + split)
// tile: 32 k-rows x 64 n-cols
__global__ void wsplit_kernel(const float* __restrict__ W,
                              __nv_bfloat16* __restrict__ Whi,
                              __nv_bfloat16* __restrict__ Wlo, int K, int N) {
    __shared__ float ts[32][65];
    int e = blockIdx.z, n0 = blockIdx.x * 64, k0 = blockIdx.y * 32;
    const float* Wp = W + (size_t)e * K * N;
#pragma unroll
    for (int i = 0; i < 4; i++) {
        int e2 = threadIdx.x + 256 * i;       // 1024 float2 slots
        int k = e2 >> 5, n2 = e2 & 31;
        float2 v = *reinterpret_cast<const float2*>(Wp + (size_t)(k0 + k) * N + n0 + n2 * 2);
        ts[k][n2 * 2] = v.x;
        ts[k][n2 * 2 + 1] = v.y;
    }
    __syncthreads();
#pragma unroll
    for (int i = 0; i < 4; i++) {
        int s2 = threadIdx.x + 256 * i;       // 1024 write slots (2 k each)
        int n = s2 >> 4, kp = (s2 & 15) * 2;
        float v0 = ts[kp][n], v1 = ts[kp + 1][n];
        __nv_bfloat16 h0 = __float2bfloat16(v0);
        __nv_bfloat16 h1 = __float2bfloat16(v1);
        size_t o = ((size_t)e * N + n0 + n) * K + k0 + kp;
        __nv_bfloat162 hv; hv.x = h0; hv.y = h1;
        *reinterpret_cast<__nv_bfloat162*>(Whi + o) = hv;
        __nv_bfloat162 lv;
        lv.x = __float2bfloat16(v0 - __bfloat162float(h0));
        lv.y = __float2bfloat16(v1 - __bfloat162float(h1));
        *reinterpret_cast<__nv_bfloat162*>(Wlo + o) = lv;
    }
}

// swizzled smem byte offset within a [rows x 32] bf16 array (64B rows)
__device__ __forceinline__ uint32_t sw_off(int row, int chunk) {
    return (uint32_t)(row * 64 + ((chunk ^ ((row >> 1) & 3)) << 4));
}

// ---------------- HMMA grouped GEMM ----------------
// D[tok, n0:n0+256] = act( A[tok,:] @ W[e][n][k]^T + bias[e] )
template <int KDIM, int NDIM, bool SPLIT_OUT>
__global__ __launch_bounds__(256, 1)
void moe_mma_kernel(const __nv_bfloat16* __restrict__ Ahi,
                    const __nv_bfloat16* __restrict__ Alo,
                    const __nv_bfloat16* __restrict__ Whi,
                    const __nv_bfloat16* __restrict__ Wlo,
                    const float* __restrict__ bias,
                    __nv_bfloat16* __restrict__ OutHi,
                    __nv_bfloat16* __restrict__ OutLo,
                    float* __restrict__ OutF) {
    extern __shared__ __align__(1024) char smem[];
    const int e = blockIdx.z;
    const int mcnt = g_cnt[e];
    const int m0 = blockIdx.y * TM;
    if (m0 >= mcnt) return;
    const int n0 = blockIdx.x * TN;
    const int tid = threadIdx.x;
    const uint32_t sb = smem_u32(smem);

    int* rowtok = (int*)(smem + SM_ROWTOK);
    float* bias_s = (float*)(smem + SM_BIAS);
    if (tid < TM) {
        int gm = m0 + tid;
        rowtok[tid] = g_bucket[e][gm < mcnt ? gm : m0];
    }
    bias_s[tid] = bias[(size_t)e * NDIM + n0 + tid];
    __syncthreads();

    // ---- A loader: thread t -> row t>>1, chunks (t&1)*2 + {0,1} ----
    const int ldr = tid >> 1;
    const int ldc = (tid & 1) * 2;
    const int atok = rowtok[ldr];
    const __nv_bfloat16* aHiSrc = Ahi + (size_t)atok * KDIM + ldc * 8;
    const __nv_bfloat16* aLoSrc = Alo + (size_t)atok * KDIM + ldc * 8;
    const uint32_t ad0 = sw_off(ldr, ldc);
    const uint32_t ad1 = sw_off(ldr, ldc + 1);
    // ---- B loader: thread t -> row t, 4 chunks ----
    const __nv_bfloat16* bHiSrc = Whi + ((size_t)e * NDIM + n0 + tid) * KDIM;
    const __nv_bfloat16* bLoSrc = Wlo + ((size_t)e * NDIM + n0 + tid) * KDIM;
    uint32_t bD[4];
#pragma unroll
    for (int c = 0; c < 4; c++) bD[c] = sw_off(tid, c);

    constexpr int NST = KDIM / TK;

    auto load_stage = [&](int s) {
        const uint32_t base = sb + SM_STAGE + (s % NSTAGE) * STAGE_BYTES;
        const int k0 = s * TK;
        cp16(base + OFF_AH + ad0, aHiSrc + k0);
        cp16(base + OFF_AH + ad1, aHiSrc + k0 + 8);
        cp16(base + OFF_AL + ad0, aLoSrc + k0);
        cp16(base + OFF_AL + ad1, aLoSrc + k0 + 8);
#pragma unroll
        for (int c = 0; c < 4; c++) {
            cp16(base + OFF_BH + bD[c], bHiSrc + k0 + c * 8);
            cp16(base + OFF_BL + bD[c], bLoSrc + k0 + c * 8);
        }
        cp_commit();
    };

    // ---- mma mapping: 2x4 warp grid, warp tile 64x64 ----
    const int wid = tid >> 5;
    const int lane = tid & 31;
    const int warp_m = wid >> 2;          // 0..1
    const int warp_n = wid & 3;           // 0..3
    const int rA = warp_m * 64 + (lane & 15);
    const int rB = warp_n * 64 + (lane & 15);
    const int csel = lane >> 4;
    const int sA = (rA >> 1) & 3;
    const int sB = (rB >> 1) & 3;

    float acc[4][8][4];
#pragma unroll
    for (int i = 0; i < 4; i++)
#pragma unroll
        for (int j = 0; j < 8; j++)
#pragma unroll
            for (int r = 0; r < 4; r++) acc[i][j][r] = 0.f;

    load_stage(0);
    load_stage(1);
    load_stage(2);

    for (int s = 0; s < NST; s++) {
        if (s >= NST - 3) cp_wait<0>(); else cp_wait<2>();
        __syncthreads();
        if (s + 3 < NST) load_stage(s + 3);

        const uint32_t base = sb + SM_STAGE + (s % NSTAGE) * STAGE_BYTES;
#pragma unroll
        for (int ks = 0; ks < 2; ks++) {
            const int c0 = ks * 2;
            uint32_t ah[4][4], al[4][4];
#pragma unroll
            for (int mt = 0; mt < 4; mt++) {
                uint32_t ad = base + (uint32_t)((rA + mt * 16) * 64) +
                              (uint32_t)(((c0 + csel) ^ sA) << 4);
                LDSM4(ah[mt][0], ah[mt][1], ah[mt][2], ah[mt][3], ad + OFF_AH);
                LDSM4(al[mt][0], al[mt][1], al[mt][2], al[mt][3], ad + OFF_AL);
            }
#pragma unroll
            for (int nh = 0; nh < 2; nh++) {
                uint32_t bh[4][2], bl[4][2];
#pragma unroll
                for (int np = 0; np < 2; np++) {
                    uint32_t bd = base + (uint32_t)((rB + nh * 32 + np * 16) * 64) +
                                  (uint32_t)(((c0 + csel) ^ sB) << 4);
                    uint32_t t0, t1, t2, t3;
                    LDSM4(t0, t1, t2, t3, bd + OFF_BH);
                    bh[2 * np][0] = t0; bh[2 * np + 1][0] = t1;
                    bh[2 * np][1] = t2; bh[2 * np + 1][1] = t3;
                    LDSM4(t0, t1, t2, t3, bd + OFF_BL);
                    bl[2 * np][0] = t0; bl[2 * np + 1][0] = t1;
                    bl[2 * np][1] = t2; bl[2 * np + 1][1] = t3;
                }
#pragma unroll
                for (int mt = 0; mt < 4; mt++)
#pragma unroll
                    for (int j = 0; j < 4; j++) {
                        const int nt = nh * 4 + j;
                        MMA16816(acc[mt][nt], ah[mt], bh[j]);
                        MMA16816(acc[mt][nt], ah[mt], bl[j]);
                        MMA16816(acc[mt][nt], al[mt], bh[j]);
                    }
            }
        }
    }

    // ---- epilogue ----
#pragma unroll
    for (int mt = 0; mt < 4; mt++) {
        const int row0 = warp_m * 64 + mt * 16 + (lane >> 2);
#pragma unroll
        for (int h = 0; h < 2; h++) {
            const int lrow = row0 + 8 * h;
            if (m0 + lrow >= mcnt) continue;
            const int tok = rowtok[lrow];
#pragma unroll
            for (int nt = 0; nt < 8; nt++) {
                const int col = warp_n * 64 + nt * 8 + (lane & 3) * 2;
                float v0 = acc[mt][nt][2 * h] + bias_s[col];
                float v1 = acc[mt][nt][2 * h + 1] + bias_s[col + 1];
                const size_t o = (size_t)tok * NDIM + n0 + col;
                if (SPLIT_OUT) {
                    v0 = fmaxf(v0, 0.f);
                    v1 = fmaxf(v1, 0.f);
                    __nv_bfloat16 h0 = __float2bfloat16(v0);
                    __nv_bfloat16 h1 = __float2bfloat16(v1);
                    __nv_bfloat162 hv; hv.x = h0; hv.y = h1;
                    *reinterpret_cast<__nv_bfloat162*>(OutHi + o) = hv;
                    __nv_bfloat162 lv;
                    lv.x = __float2bfloat16(v0 - __bfloat162float(h0));
                    lv.y = __float2bfloat16(v1 - __bfloat162float(h1));
                    *reinterpret_cast<__nv_bfloat162*>(OutLo + o) = lv;
                } else {
                    float2 f2 = make_float2(v0, v1);
                    *reinterpret_cast<float2*>(OutF + o) = f2;
                }
            }
        }
    }
}

// ---------------- launch ----------------
extern "C" void kernel_launch(void* const* d_in, const int* in_sizes, int n_in,
                              void* d_out, int out_size) {
    const float* x  = (const float*)d_in[0];
    const float* w1 = (const float*)d_in[1];
    const float* b1 = (const float*)d_in[2];
    const float* w2 = (const float*)d_in[3];
    const float* b2 = (const float*)d_in[4];
    const float* gw = (const float*)d_in[5];
    const float* gb = (const float*)d_in[6];
    float* out = (float*)d_out;

    cudaFuncSetAttribute(moe_mma_kernel<DM, DF, true>,
                         cudaFuncAttributeMaxDynamicSharedMemorySize, SMEM_TOTAL);
    cudaFuncSetAttribute(moe_mma_kernel<DF, DM, false>,
                         cudaFuncAttributeMaxDynamicSharedMemorySize, SMEM_TOTAL);

    __nv_bfloat16 *xhi, *xlo, *hhi, *hlo, *w1hi, *w1lo, *w2hi, *w2lo;
    cudaGetSymbolAddress((void**)&xhi, g_xhi);
    cudaGetSymbolAddress((void**)&xlo, g_xlo);
    cudaGetSymbolAddress((void**)&hhi, g_hhi);
    cudaGetSymbolAddress((void**)&hlo, g_hlo);
    cudaGetSymbolAddress((void**)&w1hi, g_w1hi);
    cudaGetSymbolAddress((void**)&w1lo, g_w1lo);
    cudaGetSymbolAddress((void**)&w2hi, g_w2hi);
    cudaGetSymbolAddress((void**)&w2lo, g_w2lo);

    zero_cnt_kernel<<<1, 32>>>();
    gate_route_kernel<<<(NT * 32 + 255) / 256, 256>>>(x, gw, gb);

    xsplit_kernel<<<2048, 256>>>(x, xhi, xlo, NT * DM / 2);
    wsplit_kernel<<<dim3(DF / 64, DM / 32, NE), 256>>>(w1, w1hi, w1lo, DM, DF);
    wsplit_kernel<<<dim3(DM / 64, DF / 32, NE), 256>>>(w2, w2hi, w2lo, DF, DM);

    // GEMM1: h = relu(x @ w1 + b1), split-bf16 output
    moe_mma_kernel<DM, DF, true>
        <<<dim3(DF / TN, NT / TM, NE), 256, SMEM_TOTAL>>>(
            xhi, xlo, w1hi, w1lo, b1, hhi, hlo, nullptr);
    // GEMM2: out = h @ w2 + b2, fp32 output
    moe_mma_kernel<DF, DM, false>
        <<<dim3(DM / TN, NT / TM, NE), 256, SMEM_TOTAL>>>(
            hhi, hlo, w2hi, w2lo, b2, nullptr, nullptr, out);
}

// round 5
// speedup vs baseline: 1.5877x; 1.5877x over previous
#include <cuda_runtime.h>
#include <cuda_fp16.h>
#include <cstdint>

#define NE 8
#define DM 1024
#define DF 4096
#define NT 8192  // B*S

// CTA tile
#define TM 128
#define TN 128
#define TK 32

// SMEM layout (bytes)
#define SM_ROWTOK 0          // 128 ints
#define SM_BIAS   512        // 128 floats
#define SM_STAGE  2048
#define OFF_AH    0
#define OFF_AL    8192
#define OFF_BH    16384
#define STAGE_BYTES 24576
#define NSTAGE 4
#define SMEM_TOTAL (SM_STAGE + NSTAGE * STAGE_BYTES)   // 100352

// ---------------- static scratch ----------------
__device__ int g_cnt[NE];
__device__ int g_bucket[NE][NT];
__device__ __align__(256) __half g_xhi[(size_t)NT * DM];
__device__ __align__(256) __half g_xlo[(size_t)NT * DM];
__device__ __align__(256) __half g_hhi[(size_t)NT * DF];
__device__ __align__(256) __half g_hlo[(size_t)NT * DF];
__device__ __align__(256) __half g_w1h[(size_t)NE * DF * DM];   // [e][n][k]
__device__ __align__(256) __half g_w2h[(size_t)NE * DM * DF];   // [e][n][k]

// ---------------- PTX helpers ----------------
__device__ __forceinline__ uint32_t smem_u32(const void* p) {
    uint32_t a;
    asm("{ .reg .u64 t; cvta.to.shared.u64 t, %1; cvt.u32.u64 %0, t; }" : "=r"(a) : "l"(p));
    return a;
}
__device__ __forceinline__ void cp16(uint32_t dst, const void* src) {
    asm volatile("cp.async.cg.shared.global [%0], [%1], 16;" :: "r"(dst), "l"(src));
}
__device__ __forceinline__ void cp_commit() { asm volatile("cp.async.commit_group;" ::: "memory"); }
template <int N>
__device__ __forceinline__ void cp_wait() { asm volatile("cp.async.wait_group %0;" :: "n"(N) : "memory"); }

#define LDSM4(r0, r1, r2, r3, addr) \
    asm volatile("ldmatrix.sync.aligned.m8n8.x4.shared.b16 {%0,%1,%2,%3}, [%4];" \
                 : "=r"(r0), "=r"(r1), "=r"(r2), "=r"(r3) : "r"(addr))

#define MMA16816(d, a, b) \
    asm volatile("mma.sync.aligned.m16n8k16.row.col.f32.f16.f16.f32 " \
                 "{%0,%1,%2,%3},{%4,%5,%6,%7},{%8,%9},{%0,%1,%2,%3};" \
                 : "+f"((d)[0]), "+f"((d)[1]), "+f"((d)[2]), "+f"((d)[3]) \
                 : "r"((a)[0]), "r"((a)[1]), "r"((a)[2]), "r"((a)[3]), \
                   "r"((b)[0]), "r"((b)[1]))

// ---------------- routing ----------------
__global__ void zero_cnt_kernel() {
    if (threadIdx.x < NE) g_cnt[threadIdx.x] = 0;
}

__global__ void gate_route_kernel(const float* __restrict__ x,
                                  const float* __restrict__ gw,
                                  const float* __restrict__ gb) {
    int gtid = blockIdx.x * blockDim.x + threadIdx.x;
    int tok = gtid >> 5;
    int lane = gtid & 31;
    if (tok >= NT) return;
    const float* xr = x + (size_t)tok * DM;
    float acc[NE];
#pragma unroll
    for (int e = 0; e < NE; e++) acc[e] = 0.f;
    for (int d = lane; d < DM; d += 32) {
        float xv = xr[d];
        const float4* g4 = reinterpret_cast<const float4*>(gw + (size_t)d * NE);
        float4 a = g4[0], b = g4[1];
        acc[0] += xv * a.x; acc[1] += xv * a.y; acc[2] += xv * a.z; acc[3] += xv * a.w;
        acc[4] += xv * b.x; acc[5] += xv * b.y; acc[6] += xv * b.z; acc[7] += xv * b.w;
    }
#pragma unroll
    for (int e = 0; e < NE; e++) {
#pragma unroll
        for (int off = 16; off > 0; off >>= 1)
            acc[e] += __shfl_down_sync(0xffffffffu, acc[e], off);
    }
    if (lane == 0) {
        int best = 0;
        float bv = acc[0] + gb[0];
#pragma unroll
        for (int e = 1; e < NE; e++) {
            float v = acc[e] + gb[e];
            if (v > bv) { bv = v; best = e; }
        }
        int pos = atomicAdd(&g_cnt[best], 1);
        g_bucket[best][pos] = tok;
    }
}

// ---------------- fp32 -> (hi,lo) fp16 split ----------------
__global__ void xsplit_kernel(const float* __restrict__ x,
                              __half* __restrict__ hi,
                              __half* __restrict__ lo, int n2) {
    for (int i = blockIdx.x * blockDim.x + threadIdx.x; i < n2; i += gridDim.x * blockDim.x) {
        float2 v = reinterpret_cast<const float2*>(x)[i];
        __half h0 = __float2half(v.x);
        __half h1 = __float2half(v.y);
        __half2 hv; hv.x = h0; hv.y = h1;
        reinterpret_cast<__half2*>(hi)[i] = hv;
        __half2 lv;
        lv.x = __float2half(v.x - __half2float(h0));
        lv.y = __float2half(v.y - __half2float(h1));
        reinterpret_cast<__half2*>(lo)[i] = lv;
    }
}

// W [e][K][N] fp32 -> Wh [e][N][K] fp16 (tiled transpose + round)
// tile: 32 k-rows x 64 n-cols
__global__ void wconv_kernel(const float* __restrict__ W,
                             __half* __restrict__ Wh, int K, int N) {
    __shared__ float ts[32][65];
    int e = blockIdx.z, n0 = blockIdx.x * 64, k0 = blockIdx.y * 32;
    const float* Wp = W + (size_t)e * K * N;
#pragma unroll
    for (int i = 0; i < 4; i++) {
        int e2 = threadIdx.x + 256 * i;       // 1024 float2 slots
        int k = e2 >> 5, n2 = e2 & 31;
        float2 v = *reinterpret_cast<const float2*>(Wp + (size_t)(k0 + k) * N + n0 + n2 * 2);
        ts[k][n2 * 2] = v.x;
        ts[k][n2 * 2 + 1] = v.y;
    }
    __syncthreads();
#pragma unroll
    for (int i = 0; i < 4; i++) {
        int s2 = threadIdx.x + 256 * i;       // 1024 write slots (2 k each)
        int n = s2 >> 4, kp = (s2 & 15) * 2;
        __half2 hv;
        hv.x = __float2half(ts[kp][n]);
        hv.y = __float2half(ts[kp + 1][n]);
        size_t o = ((size_t)e * N + n0 + n) * K + k0 + kp;
        *reinterpret_cast<__half2*>(Wh + o) = hv;
    }
}

// swizzled smem byte offset within a [rows x 32] fp16 array (64B rows, 4 chunks)
__device__ __forceinline__ uint32_t sw_off(int row, int chunk) {
    return (uint32_t)(row * 64 + ((chunk ^ ((row >> 1) & 3)) << 4));
}

// ---------------- HMMA grouped GEMM ----------------
// D[tok, n0:n0+128] = act( (Ahi+Alo)[tok,:] @ Wh[e][n][k]^T + bias[e] )
template <int KDIM, int NDIM, bool SPLIT_OUT>
__global__ __launch_bounds__(256, 1)
void moe_mma_kernel(const __half* __restrict__ Ahi,
                    const __half* __restrict__ Alo,
                    const __half* __restrict__ Wh,
                    const float* __restrict__ bias,
                    __half* __restrict__ OutHi,
                    __half* __restrict__ OutLo,
                    float* __restrict__ OutF) {
    extern __shared__ __align__(1024) char smem[];
    const int e = blockIdx.z;
    const int mcnt = g_cnt[e];
    const int m0 = blockIdx.y * TM;
    if (m0 >= mcnt) return;
    const int n0 = blockIdx.x * TN;
    const int tid = threadIdx.x;
    const uint32_t sb = smem_u32(smem);

    int* rowtok = (int*)(smem + SM_ROWTOK);
    float* bias_s = (float*)(smem + SM_BIAS);
    if (tid < TM) {
        int gm = m0 + tid;
        rowtok[tid] = g_bucket[e][gm < mcnt ? gm : m0];
        bias_s[tid] = bias[(size_t)e * NDIM + n0 + tid];
    }
    __syncthreads();

    // ---- loaders: thread t -> row t>>1, chunks (t&1)*2 + {0,1} ----
    const int ldr = tid >> 1;
    const int ldc = (tid & 1) * 2;
    const int atok = rowtok[ldr];
    const __half* aHiSrc = Ahi + (size_t)atok * KDIM + ldc * 8;
    const __half* aLoSrc = Alo + (size_t)atok * KDIM + ldc * 8;
    const __half* bSrc   = Wh + ((size_t)e * NDIM + n0 + ldr) * KDIM + ldc * 8;
    const uint32_t d0 = sw_off(ldr, ldc);
    const uint32_t d1 = sw_off(ldr, ldc + 1);

    constexpr int NST = KDIM / TK;

    auto load_stage = [&](int s) {
        const uint32_t base = sb + SM_STAGE + (s % NSTAGE) * STAGE_BYTES;
        const int k0 = s * TK;
        cp16(base + OFF_AH + d0, aHiSrc + k0);
        cp16(base + OFF_AH + d1, aHiSrc + k0 + 8);
        cp16(base + OFF_AL + d0, aLoSrc + k0);
        cp16(base + OFF_AL + d1, aLoSrc + k0 + 8);
        cp16(base + OFF_BH + d0, bSrc + k0);
        cp16(base + OFF_BH + d1, bSrc + k0 + 8);
        cp_commit();
    };

    // ---- mma mapping: 2x4 warp grid, warp tile 64x32 ----
    const int wid = tid >> 5;
    const int lane = tid & 31;
    const int warp_m = wid >> 2;          // 0..1
    const int warp_n = wid & 3;           // 0..3
    const int rA = warp_m * 64 + (lane & 15);
    const int rB = warp_n * 32 + (lane & 15);
    const int csel = lane >> 4;
    const int sA = (rA >> 1) & 3;
    const int sB = (rB >> 1) & 3;

    float acc[4][4][4];
#pragma unroll
    for (int i = 0; i < 4; i++)
#pragma unroll
        for (int j = 0; j < 4; j++)
#pragma unroll
            for (int r = 0; r < 4; r++) acc[i][j][r] = 0.f;

    load_stage(0);
    load_stage(1);
    load_stage(2);

    for (int s = 0; s < NST; s++) {
        if (s >= NST - 3) cp_wait<0>(); else cp_wait<2>();
        __syncthreads();
        if (s + 3 < NST) load_stage(s + 3);

        const uint32_t base = sb + SM_STAGE + (s % NSTAGE) * STAGE_BYTES;
#pragma unroll
        for (int ks = 0; ks < 2; ks++) {
            const int c0 = ks * 2;
            uint32_t ah[4][4], al[4][4], bh[4][2];
#pragma unroll
            for (int mt = 0; mt < 4; mt++) {
                uint32_t ad = base + (uint32_t)((rA + mt * 16) * 64) +
                              (uint32_t)(((c0 + csel) ^ sA) << 4);
                LDSM4(ah[mt][0], ah[mt][1], ah[mt][2], ah[mt][3], ad + OFF_AH);
                LDSM4(al[mt][0], al[mt][1], al[mt][2], al[mt][3], ad + OFF_AL);
            }
#pragma unroll
            for (int np = 0; np < 2; np++) {
                uint32_t bd = base + (uint32_t)((rB + np * 16) * 64) +
                              (uint32_t)(((c0 + csel) ^ sB) << 4);
                uint32_t t0, t1, t2, t3;
                LDSM4(t0, t1, t2, t3, bd + OFF_BH);
                bh[2 * np][0] = t0; bh[2 * np + 1][0] = t1;
                bh[2 * np][1] = t2; bh[2 * np + 1][1] = t3;
            }
#pragma unroll
            for (int mt = 0; mt < 4; mt++)
#pragma unroll
                for (int nt = 0; nt < 4; nt++) {
                    MMA16816(acc[mt][nt], ah[mt], bh[nt]);
                    MMA16816(acc[mt][nt], al[mt], bh[nt]);
                }
        }
    }

    // ---- epilogue ----
#pragma unroll
    for (int mt = 0; mt < 4; mt++) {
        const int row0 = warp_m * 64 + mt * 16 + (lane >> 2);
#pragma unroll
        for (int h = 0; h < 2; h++) {
            const int lrow = row0 + 8 * h;
            if (m0 + lrow >= mcnt) continue;
            const int tok = rowtok[lrow];
#pragma unroll
            for (int nt = 0; nt < 4; nt++) {
                const int col = warp_n * 32 + nt * 8 + (lane & 3) * 2;
                float v0 = acc[mt][nt][2 * h] + bias_s[col];
                float v1 = acc[mt][nt][2 * h + 1] + bias_s[col + 1];
                const size_t o = (size_t)tok * NDIM + n0 + col;
                if (SPLIT_OUT) {
                    v0 = fmaxf(v0, 0.f);
                    v1 = fmaxf(v1, 0.f);
                    __half h0 = __float2half(v0);
                    __half h1 = __float2half(v1);
                    __half2 hv; hv.x = h0; hv.y = h1;
                    *reinterpret_cast<__half2*>(OutHi + o) = hv;
                    __half2 lv;
                    lv.x = __float2half(v0 - __half2float(h0));
                    lv.y = __float2half(v1 - __half2float(h1));
                    *reinterpret_cast<__half2*>(OutLo + o) = lv;
                } else {
                    float2 f2 = make_float2(v0, v1);
                    *reinterpret_cast<float2*>(OutF + o) = f2;
                }
            }
        }
    }
}

// ---------------- launch ----------------
extern "C" void kernel_launch(void* const* d_in, const int* in_sizes, int n_in,
                              void* d_out, int out_size) {
    const float* x  = (const float*)d_in[0];
    const float* w1 = (const float*)d_in[1];
    const float* b1 = (const float*)d_in[2];
    const float* w2 = (const float*)d_in[3];
    const float* b2 = (const float*)d_in[4];
    const float* gw = (const float*)d_in[5];
    const float* gb = (const float*)d_in[6];
    float* out = (float*)d_out;

    cudaFuncSetAttribute(moe_mma_kernel<DM, DF, true>,
                         cudaFuncAttributeMaxDynamicSharedMemorySize, SMEM_TOTAL);
    cudaFuncSetAttribute(moe_mma_kernel<DF, DM, false>,
                         cudaFuncAttributeMaxDynamicSharedMemorySize, SMEM_TOTAL);

    __half *xhi, *xlo, *hhi, *hlo, *w1h, *w2h;
    cudaGetSymbolAddress((void**)&xhi, g_xhi);
    cudaGetSymbolAddress((void**)&xlo, g_xlo);
    cudaGetSymbolAddress((void**)&hhi, g_hhi);
    cudaGetSymbolAddress((void**)&hlo, g_hlo);
    cudaGetSymbolAddress((void**)&w1h, g_w1h);
    cudaGetSymbolAddress((void**)&w2h, g_w2h);

    zero_cnt_kernel<<<1, 32>>>();
    gate_route_kernel<<<(NT * 32 + 255) / 256, 256>>>(x, gw, gb);

    xsplit_kernel<<<2048, 256>>>(x, xhi, xlo, NT * DM / 2);
    wconv_kernel<<<dim3(DF / 64, DM / 32, NE), 256>>>(w1, w1h, DM, DF);
    wconv_kernel<<<dim3(DM / 64, DF / 32, NE), 256>>>(w2, w2h, DF, DM);

    // GEMM1: h = relu(x @ w1 + b1), split-fp16 output
    moe_mma_kernel<DM, DF, true>
        <<<dim3(DF / TN, NT / TM, NE), 256, SMEM_TOTAL>>>(
            xhi, xlo, w1h, b1, hhi, hlo, nullptr);
    // GEMM2: out = h @ w2 + b2, fp32 output
    moe_mma_kernel<DF, DM, false>
        <<<dim3(DM / TN, NT / TM, NE), 256, SMEM_TOTAL>>>(
            hhi, hlo, w2h, b2, nullptr, nullptr, out);
}

// round 6
// speedup vs baseline: 2.6288x; 1.6557x over previous
#include <cuda_runtime.h>
#include <cuda_fp16.h>
#include <cstdint>

#define NE 8
#define DM 1024
#define DF 4096
#define NT 8192  // B*S

// CTA tile
#define TM 128
#define TN 128
#define TK 32

// SMEM layout (bytes)
#define SM_ROWTOK 0          // 128 ints
#define SM_BIAS   512        // 128 floats
#define SM_STAGE  2048
#define OFF_AH    0
#define OFF_BH    8192
#define STAGE_BYTES 16384
#define NSTAGE 4
#define SMEM_TOTAL (SM_STAGE + NSTAGE * STAGE_BYTES)   // 67584

// ---------------- static scratch ----------------
__device__ int g_cnt[NE];
__device__ int g_bucket[NE][NT];
__device__ __align__(256) __half g_xh[(size_t)NT * DM];
__device__ __align__(256) __half g_hh[(size_t)NT * DF];
__device__ __align__(256) __half g_w1h[(size_t)NE * DF * DM];   // [e][n][k]
__device__ __align__(256) __half g_w2h[(size_t)NE * DM * DF];   // [e][n][k]

// ---------------- PTX helpers ----------------
__device__ __forceinline__ uint32_t smem_u32(const void* p) {
    uint32_t a;
    asm("{ .reg .u64 t; cvta.to.shared.u64 t, %1; cvt.u32.u64 %0, t; }" : "=r"(a) : "l"(p));
    return a;
}
__device__ __forceinline__ void cp16(uint32_t dst, const void* src) {
    asm volatile("cp.async.cg.shared.global [%0], [%1], 16;" :: "r"(dst), "l"(src));
}
__device__ __forceinline__ void cp_commit() { asm volatile("cp.async.commit_group;" ::: "memory"); }
template <int N>
__device__ __forceinline__ void cp_wait() { asm volatile("cp.async.wait_group %0;" :: "n"(N) : "memory"); }

#define LDSM4(r0, r1, r2, r3, addr) \
    asm volatile("ldmatrix.sync.aligned.m8n8.x4.shared.b16 {%0,%1,%2,%3}, [%4];" \
                 : "=r"(r0), "=r"(r1), "=r"(r2), "=r"(r3) : "r"(addr))

#define MMA16816(d, a, b) \
    asm volatile("mma.sync.aligned.m16n8k16.row.col.f32.f16.f16.f32 " \
                 "{%0,%1,%2,%3},{%4,%5,%6,%7},{%8,%9},{%0,%1,%2,%3};" \
                 : "+f"((d)[0]), "+f"((d)[1]), "+f"((d)[2]), "+f"((d)[3]) \
                 : "r"((a)[0]), "r"((a)[1]), "r"((a)[2]), "r"((a)[3]), \
                   "r"((b)[0]), "r"((b)[1]))

// ---------------- routing ----------------
__global__ void zero_cnt_kernel() {
    if (threadIdx.x < NE) g_cnt[threadIdx.x] = 0;
}

__global__ void gate_route_kernel(const float* __restrict__ x,
                                  const float* __restrict__ gw,
                                  const float* __restrict__ gb) {
    int gtid = blockIdx.x * blockDim.x + threadIdx.x;
    int tok = gtid >> 5;
    int lane = gtid & 31;
    if (tok >= NT) return;
    const float* xr = x + (size_t)tok * DM;
    float acc[NE];
#pragma unroll
    for (int e = 0; e < NE; e++) acc[e] = 0.f;
    for (int d = lane; d < DM; d += 32) {
        float xv = xr[d];
        const float4* g4 = reinterpret_cast<const float4*>(gw + (size_t)d * NE);
        float4 a = g4[0], b = g4[1];
        acc[0] += xv * a.x; acc[1] += xv * a.y; acc[2] += xv * a.z; acc[3] += xv * a.w;
        acc[4] += xv * b.x; acc[5] += xv * b.y; acc[6] += xv * b.z; acc[7] += xv * b.w;
    }
#pragma unroll
    for (int e = 0; e < NE; e++) {
#pragma unroll
        for (int off = 16; off > 0; off >>= 1)
            acc[e] += __shfl_down_sync(0xffffffffu, acc[e], off);
    }
    if (lane == 0) {
        int best = 0;
        float bv = acc[0] + gb[0];
#pragma unroll
        for (int e = 1; e < NE; e++) {
            float v = acc[e] + gb[e];
            if (v > bv) { bv = v; best = e; }
        }
        int pos = atomicAdd(&g_cnt[best], 1);
        g_bucket[best][pos] = tok;
    }
}

// ---------------- fp32 -> fp16 ----------------
__global__ void xconv_kernel(const float* __restrict__ x,
                             __half* __restrict__ h, int n2) {
    for (int i = blockIdx.x * blockDim.x + threadIdx.x; i < n2; i += gridDim.x * blockDim.x) {
        float2 v = reinterpret_cast<const float2*>(x)[i];
        __half2 hv;
        hv.x = __float2half(v.x);
        hv.y = __float2half(v.y);
        reinterpret_cast<__half2*>(h)[i] = hv;
    }
}

// W [e][K][N] fp32 -> Wh [e][N][K] fp16 (tiled transpose + round)
__global__ void wconv_kernel(const float* __restrict__ W,
                             __half* __restrict__ Wh, int K, int N) {
    __shared__ float ts[32][65];
    int e = blockIdx.z, n0 = blockIdx.x * 64, k0 = blockIdx.y * 32;
    const float* Wp = W + (size_t)e * K * N;
#pragma unroll
    for (int i = 0; i < 4; i++) {
        int e2 = threadIdx.x + 256 * i;       // 1024 float2 slots
        int k = e2 >> 5, n2 = e2 & 31;
        float2 v = *reinterpret_cast<const float2*>(Wp + (size_t)(k0 + k) * N + n0 + n2 * 2);
        ts[k][n2 * 2] = v.x;
        ts[k][n2 * 2 + 1] = v.y;
    }
    __syncthreads();
#pragma unroll
    for (int i = 0; i < 4; i++) {
        int s2 = threadIdx.x + 256 * i;       // 1024 write slots (2 k each)
        int n = s2 >> 4, kp = (s2 & 15) * 2;
        __half2 hv;
        hv.x = __float2half(ts[kp][n]);
        hv.y = __float2half(ts[kp + 1][n]);
        size_t o = ((size_t)e * N + n0 + n) * K + k0 + kp;
        *reinterpret_cast<__half2*>(Wh + o) = hv;
    }
}

// swizzled smem byte offset within a [rows x 32] fp16 array (64B rows, 4 chunks)
__device__ __forceinline__ uint32_t sw_off(int row, int chunk) {
    return (uint32_t)(row * 64 + ((chunk ^ ((row >> 1) & 3)) << 4));
}

// ---------------- HMMA grouped GEMM ----------------
// D[tok, n0:n0+128] = act( A[tok,:] @ Wh[e][n][k]^T + bias[e] )
template <int KDIM, int NDIM, bool RELU_H>
__global__ __launch_bounds__(256, 2)
void moe_mma_kernel(const __half* __restrict__ A,
                    const __half* __restrict__ Wh,
                    const float* __restrict__ bias,
                    __half* __restrict__ OutH,
                    float* __restrict__ OutF) {
    extern __shared__ __align__(1024) char smem[];
    const int e = blockIdx.z;
    const int mcnt = g_cnt[e];
    const int m0 = blockIdx.y * TM;
    if (m0 >= mcnt) return;
    const int n0 = blockIdx.x * TN;
    const int tid = threadIdx.x;
    const uint32_t sb = smem_u32(smem);

    int* rowtok = (int*)(smem + SM_ROWTOK);
    float* bias_s = (float*)(smem + SM_BIAS);
    if (tid < TM) {
        int gm = m0 + tid;
        rowtok[tid] = g_bucket[e][gm < mcnt ? gm : m0];
        bias_s[tid] = bias[(size_t)e * NDIM + n0 + tid];
    }
    __syncthreads();

    // ---- loaders: thread t -> row t>>1, chunks (t&1)*2 + {0,1} ----
    const int ldr = tid >> 1;
    const int ldc = (tid & 1) * 2;
    const int atok = rowtok[ldr];
    const __half* aSrc = A + (size_t)atok * KDIM + ldc * 8;
    const __half* bSrc = Wh + ((size_t)e * NDIM + n0 + ldr) * KDIM + ldc * 8;
    const uint32_t d0 = sw_off(ldr, ldc);
    const uint32_t d1 = sw_off(ldr, ldc + 1);

    constexpr int NST = KDIM / TK;

    auto load_stage = [&](int s) {
        const uint32_t base = sb + SM_STAGE + (s % NSTAGE) * STAGE_BYTES;
        const int k0 = s * TK;
        cp16(base + OFF_AH + d0, aSrc + k0);
        cp16(base + OFF_AH + d1, aSrc + k0 + 8);
        cp16(base + OFF_BH + d0, bSrc + k0);
        cp16(base + OFF_BH + d1, bSrc + k0 + 8);
        cp_commit();
    };

    // ---- mma mapping: 2x4 warp grid, warp tile 64x32 ----
    const int wid = tid >> 5;
    const int lane = tid & 31;
    const int warp_m = wid >> 2;          // 0..1
    const int warp_n = wid & 3;           // 0..3
    const int rA = warp_m * 64 + (lane & 15);
    const int rB = warp_n * 32 + (lane & 15);
    const int csel = lane >> 4;
    const int sA = (rA >> 1) & 3;
    const int sB = (rB >> 1) & 3;

    float acc[4][4][4];
#pragma unroll
    for (int i = 0; i < 4; i++)
#pragma unroll
        for (int j = 0; j < 4; j++)
#pragma unroll
            for (int r = 0; r < 4; r++) acc[i][j][r] = 0.f;

    load_stage(0);
    load_stage(1);
    load_stage(2);

    for (int s = 0; s < NST; s++) {
        if (s >= NST - 3) cp_wait<0>(); else cp_wait<2>();
        __syncthreads();
        if (s + 3 < NST) load_stage(s + 3);

        const uint32_t base = sb + SM_STAGE + (s % NSTAGE) * STAGE_BYTES;
#pragma unroll
        for (int ks = 0; ks < 2; ks++) {
            const int c0 = ks * 2;
            uint32_t ah[4][4], bh[4][2];
#pragma unroll
            for (int mt = 0; mt < 4; mt++) {
                uint32_t ad = base + (uint32_t)((rA + mt * 16) * 64) +
                              (uint32_t)(((c0 + csel) ^ sA) << 4);
                LDSM4(ah[mt][0], ah[mt][1], ah[mt][2], ah[mt][3], ad + OFF_AH);
            }
#pragma unroll
            for (int np = 0; np < 2; np++) {
                uint32_t bd = base + (uint32_t)((rB + np * 16) * 64) +
                              (uint32_t)(((c0 + csel) ^ sB) << 4);
                uint32_t t0, t1, t2, t3;
                LDSM4(t0, t1, t2, t3, bd + OFF_BH);
                bh[2 * np][0] = t0; bh[2 * np + 1][0] = t1;
                bh[2 * np][1] = t2; bh[2 * np + 1][1] = t3;
            }
#pragma unroll
            for (int mt = 0; mt < 4; mt++)
#pragma unroll
                for (int nt = 0; nt < 4; nt++)
                    MMA16816(acc[mt][nt], ah[mt], bh[nt]);
        }
    }

    // ---- epilogue ----
#pragma unroll
    for (int mt = 0; mt < 4; mt++) {
        const int row0 = warp_m * 64 + mt * 16 + (lane >> 2);
#pragma unroll
        for (int h = 0; h < 2; h++) {
            const int lrow = row0 + 8 * h;
            if (m0 + lrow >= mcnt) continue;
            const int tok = rowtok[lrow];
#pragma unroll
            for (int nt = 0; nt < 4; nt++) {
                const int col = warp_n * 32 + nt * 8 + (lane & 3) * 2;
                float v0 = acc[mt][nt][2 * h] + bias_s[col];
                float v1 = acc[mt][nt][2 * h + 1] + bias_s[col + 1];
                const size_t o = (size_t)tok * NDIM + n0 + col;
                if (RELU_H) {
                    v0 = fmaxf(v0, 0.f);
                    v1 = fmaxf(v1, 0.f);
                    __half2 hv;
                    hv.x = __float2half(v0);
                    hv.y = __float2half(v1);
                    *reinterpret_cast<__half2*>(OutH + o) = hv;
                } else {
                    float2 f2 = make_float2(v0, v1);
                    *reinterpret_cast<float2*>(OutF + o) = f2;
                }
            }
        }
    }
}

// ---------------- launch ----------------
extern "C" void kernel_launch(void* const* d_in, const int* in_sizes, int n_in,
                              void* d_out, int out_size) {
    const float* x  = (const float*)d_in[0];
    const float* w1 = (const float*)d_in[1];
    const float* b1 = (const float*)d_in[2];
    const float* w2 = (const float*)d_in[3];
    const float* b2 = (const float*)d_in[4];
    const float* gw = (const float*)d_in[5];
    const float* gb = (const float*)d_in[6];
    float* out = (float*)d_out;

    cudaFuncSetAttribute(moe_mma_kernel<DM, DF, true>,
                         cudaFuncAttributeMaxDynamicSharedMemorySize, SMEM_TOTAL);
    cudaFuncSetAttribute(moe_mma_kernel<DF, DM, false>,
                         cudaFuncAttributeMaxDynamicSharedMemorySize, SMEM_TOTAL);

    __half *xh, *hh, *w1h, *w2h;
    cudaGetSymbolAddress((void**)&xh, g_xh);
    cudaGetSymbolAddress((void**)&hh, g_hh);
    cudaGetSymbolAddress((void**)&w1h, g_w1h);
    cudaGetSymbolAddress((void**)&w2h, g_w2h);

    zero_cnt_kernel<<<1, 32>>>();
    gate_route_kernel<<<(NT * 32 + 255) / 256, 256>>>(x, gw, gb);

    xconv_kernel<<<2048, 256>>>(x, xh, NT * DM / 2);
    wconv_kernel<<<dim3(DF / 64, DM / 32, NE), 256>>>(w1, w1h, DM, DF);
    wconv_kernel<<<dim3(DM / 64, DF / 32, NE), 256>>>(w2, w2h, DF, DM);

    // GEMM1: h = relu(x @ w1 + b1), fp16 output
    moe_mma_kernel<DM, DF, true>
        <<<dim3(DF / TN, NT / TM, NE), 256, SMEM_TOTAL>>>(xh, w1h, b1, hh, nullptr);
    // GEMM2: out = h @ w2 + b2, fp32 output
    moe_mma_kernel<DF, DM, false>
        <<<dim3(DM / TN, NT / TM, NE), 256, SMEM_TOTAL>>>(hh, w2h, b2, nullptr, out);
}